// round 12
// baseline (speedup 1.0000x reference)
#include <cuda_runtime.h>
#include <cuda_bf16.h>

#define NMIX 160
// gemm1: 64m x 160n, KC=64, 512 threads = 4m x 4n warps, j=5 (tf32)
#define T1    512
#define BM1   64
#define KC1   64
#define A1PAD 68
#define B1PAD 168
#define XK_SZ (BM1 * A1PAD)
#define W1_SZ (KC1 * B1PAD)
#define SM1_FLOATS (2 * XK_SZ + 2 * W1_SZ)       // 120832 B
// gemm2: 64m x 256d blocks; bf16 m16n8k16; W2 in 32-wide chunks
#define T2    256
#define BM2   64
#define BN2   256
#define CW    32
#define NCH   (BN2 / CW)             // 8
#define HP32  104                    // hp row pitch in u32 (mod 32 = 8 banks)
#define WP32  104                    // w2s row pitch in u32
#define YP    36
#define HP_TOT (BM2 * HP32)                      // 6656 u32
#define WP_TOT (CW * WP32)                       // 3328 u32
#define YS_TOT (5 * BM2 * YP)                    // 11520 f32
#define SM2_WORDS (HP_TOT + WP_TOT + YS_TOT)     // 21504 -> 86016 B

// h = tanh(xk @ W1) packed bf16x2: [M][80] u32, M = 8192
__device__ unsigned g_h32[8192 * 80];

__device__ __forceinline__ void mma_tf32(float* c, const float4& a, const float2& b) {
    const unsigned* A = reinterpret_cast<const unsigned*>(&a);
    const unsigned* B = reinterpret_cast<const unsigned*>(&b);
    asm volatile(
        "mma.sync.aligned.m16n8k8.row.col.f32.tf32.tf32.f32 "
        "{%0,%1,%2,%3},{%4,%5,%6,%7},{%8,%9},{%0,%1,%2,%3};"
        : "+f"(c[0]), "+f"(c[1]), "+f"(c[2]), "+f"(c[3])
        : "r"(A[0]), "r"(A[1]), "r"(A[2]), "r"(A[3]), "r"(B[0]), "r"(B[1]));
}

__device__ __forceinline__ void mma_bf16(float* c, unsigned a0, unsigned a1,
                                         unsigned a2, unsigned a3,
                                         unsigned b0, unsigned b1) {
    asm volatile(
        "mma.sync.aligned.m16n8k16.row.col.f32.bf16.bf16.f32 "
        "{%0,%1,%2,%3},{%4,%5,%6,%7},{%8,%9},{%0,%1,%2,%3};"
        : "+f"(c[0]), "+f"(c[1]), "+f"(c[2]), "+f"(c[3])
        : "r"(a0), "r"(a1), "r"(a2), "r"(a3), "r"(b0), "r"(b1));
}

__device__ __forceinline__ unsigned packbf(float lo, float hi) {
    __nv_bfloat162 v = __float22bfloat162_rn(make_float2(lo, hi));
    return *reinterpret_cast<unsigned*>(&v);
}

// ---------------------------------------------------------------------------
// GEMM1 (tf32): g_h32[m][:] = bf16( tanh( sum_k xk[m,k] * W1[k,n] ) )
// ---------------------------------------------------------------------------
__global__ void __launch_bounds__(T1, 1) k_gemm1(
    const float* __restrict__ x, const float* __restrict__ state,
    const float* __restrict__ tmx, const float* __restrict__ W1,
    const int* __restrict__ i_ptr, int S, int D, int rows)
{
    extern __shared__ float sm[];

    const int m0g  = blockIdx.x * BM1;
    const int tid  = threadIdx.x;
    const int w    = tid >> 5;
    const int lane = tid & 31;
    const int wm   = w & 3;
    const int wn   = w >> 2;
    const int gq   = lane >> 2;
    const int tig  = lane & 3;
    const int i1   = rows * i_ptr[0] + 1;

    const int sa_m  = tid >> 4;
    const int sa_kq = (tid & 15) * 4;

    float acc[5][4];
#pragma unroll
    for (int j = 0; j < 5; j++)
#pragma unroll
        for (int q = 0; q < 4; q++) acc[j][q] = 0.f;

    float4 xv[2], pv[2], tv[2];
    float4 wv[5];
    int    wk[5], wn4[5];

    const int nc = D / KC1;

#define LDG1(KB)                                                              \
    {                                                                         \
        _Pragma("unroll")                                                     \
        for (int it = 0; it < 2; it++) {                                      \
            int m  = sa_m + it * 32;                                          \
            int mg = m0g + m;                                                 \
            int g  = (KB) + sa_kq;                                            \
            xv[it] = *(const float4*)&x[(size_t)mg * D + g];                  \
            if ((mg % S) == 0) {                                              \
                int b = mg / S;                                               \
                pv[it] = *(const float4*)&state[((size_t)b * rows + i1) * D + g]; \
            } else {                                                          \
                pv[it] = *(const float4*)&x[(size_t)(mg - 1) * D + g];        \
            }                                                                 \
            tv[it] = *(const float4*)&tmx[g];                                 \
        }                                                                     \
        _Pragma("unroll")                                                     \
        for (int it = 0; it < 5; it++) {                                      \
            int idx = tid + it * T1;                                          \
            int k   = idx / 40;                                               \
            int n4  = (idx - k * 40) * 4;                                     \
            wk[it] = k; wn4[it] = n4;                                         \
            wv[it] = *(const float4*)&W1[(size_t)((KB) + k) * NMIX + n4];     \
        }                                                                     \
    }

#define STS1(BUF)                                                             \
    {                                                                         \
        float* xb = sm + (BUF) * XK_SZ;                                       \
        float* wb = sm + 2 * XK_SZ + (BUF) * W1_SZ;                           \
        _Pragma("unroll")                                                     \
        for (int it = 0; it < 2; it++) {                                      \
            int m = sa_m + it * 32;                                           \
            float4 v;                                                         \
            v.x = xv[it].x + (pv[it].x - xv[it].x) * tv[it].x;                \
            v.y = xv[it].y + (pv[it].y - xv[it].y) * tv[it].y;                \
            v.z = xv[it].z + (pv[it].z - xv[it].z) * tv[it].z;                \
            v.w = xv[it].w + (pv[it].w - xv[it].w) * tv[it].w;                \
            *(float4*)&xb[m * A1PAD + sa_kq] = v;                             \
        }                                                                     \
        _Pragma("unroll")                                                     \
        for (int it = 0; it < 5; it++)                                        \
            *(float4*)&wb[wk[it] * B1PAD + wn4[it]] = wv[it];                 \
    }

    LDG1(0);

    for (int c = 0; c < nc; c++) {
        STS1(c & 1);
        __syncthreads();
        if (c + 1 < nc) LDG1((c + 1) * KC1);

        const float* xb = sm + (c & 1) * XK_SZ;
        const float* wb = sm + 2 * XK_SZ + (c & 1) * W1_SZ;
        const int r0 = wm * 16 + gq;
#pragma unroll
        for (int ks = 0; ks < 8; ks++) {
            const int k0 = ks * 8;
            float4 af;
            af.x = xb[r0 * A1PAD + k0 + tig];
            af.y = xb[(r0 + 8) * A1PAD + k0 + tig];
            af.z = xb[r0 * A1PAD + k0 + tig + 4];
            af.w = xb[(r0 + 8) * A1PAD + k0 + tig + 4];
#pragma unroll
            for (int j = 0; j < 5; j++) {
                const int n = wn * 40 + j * 8 + gq;
                float2 b;
                b.x = wb[(k0 + tig) * B1PAD + n];
                b.y = wb[(k0 + tig + 4) * B1PAD + n];
                mma_tf32(acc[j], af, b);
            }
        }
    }

    // epilogue: tanh -> bf16x2 -> g_h32
    const int r0g = m0g + wm * 16 + gq;
#pragma unroll
    for (int j = 0; j < 5; j++) {
        const int n2 = wn * 20 + j * 4 + tig;    // u32 col (bf16 pair)
        g_h32[(size_t)r0g * 80 + n2]       = packbf(tanhf(acc[j][0]), tanhf(acc[j][1]));
        g_h32[(size_t)(r0g + 8) * 80 + n2] = packbf(tanhf(acc[j][2]), tanhf(acc[j][3]));
    }
#undef LDG1
#undef STS1
}

// ---------------------------------------------------------------------------
// GEMM2 (bf16 m16n8k16): out[m,f,d] = x + sx*(maa_f + h_f @ W2_f)
// 64m x 256d block; paired bf16 layouts; y restage; state copy folded in.
// ---------------------------------------------------------------------------
__global__ void __launch_bounds__(T2, 2) k_gemm2(
    const float* __restrict__ x, const float* __restrict__ state,
    const float* __restrict__ W2,
    const float* __restrict__ mk, const float* __restrict__ mw,
    const float* __restrict__ mv, const float* __restrict__ mr,
    const float* __restrict__ mg,
    const int* __restrict__ i_ptr, float* __restrict__ out,
    float* __restrict__ out_state,
    int S, int D, int rows, int has_state, int total4)
{
    extern __shared__ unsigned smu[];
    unsigned* hp32  = smu;                       // [64][HP32]
    unsigned* w2s32 = smu + HP_TOT;              // [32][WP32]
    float*    ys    = (float*)(smu + HP_TOT + WP_TOT);   // [5][64][YP]

    const int m0   = blockIdx.x * BM2;
    const int d0   = blockIdx.y * BN2;
    const int tid  = threadIdx.x;
    const int w    = tid >> 5;
    const int lane = tid & 31;
    const int wm   = w & 3;          // 4 m-groups of 16
    const int wn   = w >> 2;         // 2 n-groups of 16
    const int gq   = lane >> 2;
    const int tig  = lane & 3;
    const int i1   = rows * i_ptr[0] + 1;

    // ---- state copy (distributed over all blocks) ----
    if (has_state) {
        const int nb = gridDim.x * gridDim.y;
        for (int idx = (blockIdx.y * gridDim.x + blockIdx.x) * T2 + tid;
             idx < total4; idx += nb * T2) {
            int e  = idx * 4;
            int dd = e % D;
            int r  = (e / D) % rows;
            int b  = e / (D * rows);
            float4 v;
            if (r == i1)
                v = *(const float4*)&x[((size_t)b * S + (S - 1)) * D + dd];
            else
                v = *(const float4*)&state[e];
            *(float4*)&out_state[e] = v;
        }
    }

    // ---- stage h once, paired layout:
    // src u32 p (kpair): seg=p>>3, lp=p&7 -> dst seg*8 + (lp&3)*2 + (lp>>2)
#pragma unroll
    for (int it = 0; it < 5; it++) {
        int idx = tid + it * T2;                 // 0..1279
        int r   = idx / 20;
        int q4  = (idx - r * 20) * 4;
        const uint4 hv = *(const uint4*)&g_h32[(size_t)(m0 + r) * 80 + q4];
        unsigned vals[4] = { hv.x, hv.y, hv.z, hv.w };
#pragma unroll
        for (int e = 0; e < 4; e++) {
            int p   = q4 + e;
            int seg = p >> 3, lp = p & 7;
            hp32[r * HP32 + seg * 8 + (lp & 3) * 2 + (lp >> 2)] = vals[e];
        }
    }

    const float* maa[5] = { mk, mw, mv, mr, mg };

    // epilogue mapping
    const int er  = tid >> 3;
    const int ec4 = (tid & 7) * 4;

    // W2 chunk staging: 640 groups of (kpair, 4n); <=3 per thread
    float4 wva[3], wvb[3];

#define LDGW(C)                                                               \
    {                                                                         \
        _Pragma("unroll")                                                     \
        for (int it = 0; it < 3; it++) {                                      \
            int g = tid + it * T2;                                            \
            if (g < 640) {                                                    \
                int kp = g >> 3, n4 = (g & 7) * 4;                            \
                wva[it] = *(const float4*)&W2[(size_t)(2 * kp) * D + d0 + (C) * CW + n4]; \
                wvb[it] = *(const float4*)&W2[(size_t)(2 * kp + 1) * D + d0 + (C) * CW + n4]; \
            }                                                                 \
        }                                                                     \
    }

#define STSW()                                                                \
    {                                                                         \
        _Pragma("unroll")                                                     \
        for (int it = 0; it < 3; it++) {                                      \
            int g = tid + it * T2;                                            \
            if (g < 640) {                                                    \
                int kp = g >> 3, n4 = (g & 7) * 4;                            \
                int seg = kp >> 3, lp = kp & 7;                               \
                int dst = seg * 8 + (lp & 3) * 2 + (lp >> 2);                 \
                w2s32[(n4 + 0) * WP32 + dst] = packbf(wva[it].x, wvb[it].x);  \
                w2s32[(n4 + 1) * WP32 + dst] = packbf(wva[it].y, wvb[it].y);  \
                w2s32[(n4 + 2) * WP32 + dst] = packbf(wva[it].z, wvb[it].z);  \
                w2s32[(n4 + 3) * WP32 + dst] = packbf(wva[it].w, wvb[it].w);  \
            }                                                                 \
        }                                                                     \
    }

    LDGW(0);

    for (int c = 0; c < NCH; c++) {
        STSW();
        __syncthreads();                 // (A) w2s ready; h staging (c==0)
        if (c + 1 < NCH) LDGW(c + 1);

        const int d0c = d0 + c * CW;
        const int r0  = wm * 16 + gq;

        float acc[5][2][4];
#pragma unroll
        for (int f = 0; f < 5; f++)
#pragma unroll
            for (int j = 0; j < 2; j++)
#pragma unroll
                for (int q = 0; q < 4; q++) acc[f][j][q] = 0.f;

#pragma unroll
        for (int f = 0; f < 5; f++) {
#pragma unroll
            for (int ks = 0; ks < 2; ks++) {
                const int seg = f * 2 + ks;
                const uint2 alo = *(const uint2*)&hp32[r0 * HP32 + seg * 8 + tig * 2];
                const uint2 ahi = *(const uint2*)&hp32[(r0 + 8) * HP32 + seg * 8 + tig * 2];
#pragma unroll
                for (int j = 0; j < 2; j++) {
                    const int n = wn * 16 + j * 8 + gq;
                    const uint2 bb = *(const uint2*)&w2s32[n * WP32 + seg * 8 + tig * 2];
                    mma_bf16(acc[f][j], alo.x, ahi.x, alo.y, ahi.y, bb.x, bb.y);
                }
            }
        }

        // ---- restage y fragments to smem ----
#pragma unroll
        for (int f = 0; f < 5; f++)
#pragma unroll
            for (int j = 0; j < 2; j++) {
                const int col = wn * 16 + j * 8 + tig * 2;
#pragma unroll
                for (int half = 0; half < 2; half++) {
                    const int row = wm * 16 + gq + half * 8;
                    *(float2*)&ys[(f * BM2 + row) * YP + col] =
                        make_float2(acc[f][j][half * 2], acc[f][j][half * 2 + 1]);
                }
            }
        __syncthreads();                 // (B) y ready

        // ---- coalesced epilogue ----
#pragma unroll
        for (int it = 0; it < 2; it++) {
            const int row = er + it * 32;
            const int mr_ = m0 + row;
            const float4 xvv = *(const float4*)&x[(size_t)mr_ * D + d0c + ec4];
            float4 pvv;
            if ((mr_ % S) == 0) {
                int b = mr_ / S;
                pvv = *(const float4*)&state[((size_t)b * rows + i1) * D + d0c + ec4];
            } else {
                pvv = *(const float4*)&x[(size_t)(mr_ - 1) * D + d0c + ec4];
            }
            float4 sxv;
            sxv.x = pvv.x - xvv.x; sxv.y = pvv.y - xvv.y;
            sxv.z = pvv.z - xvv.z; sxv.w = pvv.w - xvv.w;
#pragma unroll
            for (int f = 0; f < 5; f++) {
                const float4 mfv = *(const float4*)&maa[f][d0c + ec4];
                const float4 yv  = *(const float4*)&ys[(f * BM2 + row) * YP + ec4];
                float4 o;
                o.x = xvv.x + sxv.x * (mfv.x + yv.x);
                o.y = xvv.y + sxv.y * (mfv.y + yv.y);
                o.z = xvv.z + sxv.z * (mfv.z + yv.z);
                o.w = xvv.w + sxv.w * (mfv.w + yv.w);
                *(float4*)&out[((size_t)mr_ * 5 + f) * D + d0c + ec4] = o;
            }
        }
    }
#undef LDGW
#undef STSW
}

// ---------------------------------------------------------------------------
extern "C" void kernel_launch(void* const* d_in, const int* in_sizes, int n_in,
                              void* d_out, int out_size)
{
    const float* x     = (const float*)d_in[0];
    const float* state = (const float*)d_in[1];
    const float* tmx   = (const float*)d_in[2];
    const float* W1    = (const float*)d_in[3];
    const float* W2    = (const float*)d_in[4];
    const float* mk    = (const float*)d_in[5];
    const float* mw    = (const float*)d_in[6];
    const float* mv    = (const float*)d_in[7];
    const float* mr    = (const float*)d_in[8];
    const float* mg    = (const float*)d_in[9];
    const int*   ip    = (const int*)d_in[10];

    const int D    = in_sizes[2];          // 2048
    const int M    = in_sizes[0] / D;      // 8192
    const int rows = 2 + D / 32;           // 66
    const int B    = in_sizes[1] / (rows * D);
    const int S    = M / B;

    float* out_x = (float*)d_out;
    const long long xsz = (long long)M * 5 * D;
    const int has_state = ((long long)out_size > xsz) ? 1 : 0;
    float* out_state = out_x + xsz;
    const int total4 = (B * rows * D) / 4;

    const int smem1 = SM1_FLOATS * 4;      // 120832 B
    const int smem2 = SM2_WORDS * 4;       // 86016 B
    static int inited = 0;
    if (!inited) {
        cudaFuncSetAttribute(k_gemm1, cudaFuncAttributeMaxDynamicSharedMemorySize, smem1);
        cudaFuncSetAttribute(k_gemm2, cudaFuncAttributeMaxDynamicSharedMemorySize, smem2);
        inited = 1;
    }

    k_gemm1<<<M / BM1, T1, smem1>>>(x, state, tmx, W1, ip, S, D, rows);

    dim3 g2(M / BM2, D / BN2);
    k_gemm2<<<g2, T2, smem2>>>(x, state, W2, mk, mw, mv, mr, mg, ip,
                               out_x, out_state, S, D, rows,
                               has_state, total4);
}

// round 13
// speedup vs baseline: 1.0155x; 1.0155x over previous
#include <cuda_runtime.h>
#include <cuda_bf16.h>

#define NMIX 160
// gemm1: 64m x 160n, KC=64, 512 threads = 4m x 4n warps, j=5 (tf32)
#define T1    512
#define BM1   64
#define KC1   64
#define A1PAD 68
#define B1PAD 168
#define XK_SZ (BM1 * A1PAD)
#define W1_SZ (KC1 * B1PAD)
#define SM1_FLOATS (2 * XK_SZ + 2 * W1_SZ)       // 120832 B
// gemm2: 64m x 256d blocks; bf16 m16n8k16; W2 in 32-wide chunks
#define T2    256
#define BM2   64
#define BN2   256
#define CW    32
#define NCH   (BN2 / CW)             // 8
#define HP32  104                    // hp row pitch (u32)
#define WP32  104                    // w2s row pitch (u32)
#define Y2P   20                     // ys row pitch (u32, bf16x2)
#define MAPAD 260                    // maa tile row pitch (f32)
#define HP_TOT (BM2 * HP32)                      // 6656 u32
#define WP_TOT (CW * WP32)                       // 3328 u32
#define Y2_TOT (5 * BM2 * Y2P)                   // 6400 u32
#define MA_TOT (5 * MAPAD)                       // 1300 f32
#define SM2_WORDS (HP_TOT + WP_TOT + Y2_TOT + MA_TOT)  // 17684 -> 70736 B

// h = tanh(xk @ W1) packed bf16x2: [M][80] u32, M = 8192
__device__ unsigned g_h32[8192 * 80];

__device__ __forceinline__ void mma_tf32(float* c, const float4& a, const float2& b) {
    const unsigned* A = reinterpret_cast<const unsigned*>(&a);
    const unsigned* B = reinterpret_cast<const unsigned*>(&b);
    asm volatile(
        "mma.sync.aligned.m16n8k8.row.col.f32.tf32.tf32.f32 "
        "{%0,%1,%2,%3},{%4,%5,%6,%7},{%8,%9},{%0,%1,%2,%3};"
        : "+f"(c[0]), "+f"(c[1]), "+f"(c[2]), "+f"(c[3])
        : "r"(A[0]), "r"(A[1]), "r"(A[2]), "r"(A[3]), "r"(B[0]), "r"(B[1]));
}

__device__ __forceinline__ void mma_bf16(float* c, unsigned a0, unsigned a1,
                                         unsigned a2, unsigned a3,
                                         unsigned b0, unsigned b1) {
    asm volatile(
        "mma.sync.aligned.m16n8k16.row.col.f32.bf16.bf16.f32 "
        "{%0,%1,%2,%3},{%4,%5,%6,%7},{%8,%9},{%0,%1,%2,%3};"
        : "+f"(c[0]), "+f"(c[1]), "+f"(c[2]), "+f"(c[3])
        : "r"(a0), "r"(a1), "r"(a2), "r"(a3), "r"(b0), "r"(b1));
}

__device__ __forceinline__ unsigned packbf(float lo, float hi) {
    __nv_bfloat162 v = __float22bfloat162_rn(make_float2(lo, hi));
    return *reinterpret_cast<unsigned*>(&v);
}

__device__ __forceinline__ float2 unpackbf(unsigned u) {
    __nv_bfloat162 v = *reinterpret_cast<__nv_bfloat162*>(&u);
    return __bfloat1622float2(v);
}

// ---------------------------------------------------------------------------
// GEMM1 (tf32): g_h32[m][:] = bf16( tanh( sum_k xk[m,k] * W1[k,n] ) )
// ---------------------------------------------------------------------------
__global__ void __launch_bounds__(T1, 1) k_gemm1(
    const float* __restrict__ x, const float* __restrict__ state,
    const float* __restrict__ tmx, const float* __restrict__ W1,
    const int* __restrict__ i_ptr, int S, int D, int rows)
{
    extern __shared__ float sm[];

    const int m0g  = blockIdx.x * BM1;
    const int tid  = threadIdx.x;
    const int w    = tid >> 5;
    const int lane = tid & 31;
    const int wm   = w & 3;
    const int wn   = w >> 2;
    const int gq   = lane >> 2;
    const int tig  = lane & 3;
    const int i1   = rows * i_ptr[0] + 1;

    const int sa_m  = tid >> 4;
    const int sa_kq = (tid & 15) * 4;

    float acc[5][4];
#pragma unroll
    for (int j = 0; j < 5; j++)
#pragma unroll
        for (int q = 0; q < 4; q++) acc[j][q] = 0.f;

    float4 xv[2], pv[2], tv[2];
    float4 wv[5];
    int    wk[5], wn4[5];

    const int nc = D / KC1;

#define LDG1(KB)                                                              \
    {                                                                         \
        _Pragma("unroll")                                                     \
        for (int it = 0; it < 2; it++) {                                      \
            int m  = sa_m + it * 32;                                          \
            int mg = m0g + m;                                                 \
            int g  = (KB) + sa_kq;                                            \
            xv[it] = *(const float4*)&x[(size_t)mg * D + g];                  \
            if ((mg % S) == 0) {                                              \
                int b = mg / S;                                               \
                pv[it] = *(const float4*)&state[((size_t)b * rows + i1) * D + g]; \
            } else {                                                          \
                pv[it] = *(const float4*)&x[(size_t)(mg - 1) * D + g];        \
            }                                                                 \
            tv[it] = *(const float4*)&tmx[g];                                 \
        }                                                                     \
        _Pragma("unroll")                                                     \
        for (int it = 0; it < 5; it++) {                                      \
            int idx = tid + it * T1;                                          \
            int k   = idx / 40;                                               \
            int n4  = (idx - k * 40) * 4;                                     \
            wk[it] = k; wn4[it] = n4;                                         \
            wv[it] = *(const float4*)&W1[(size_t)((KB) + k) * NMIX + n4];     \
        }                                                                     \
    }

#define STS1(BUF)                                                             \
    {                                                                         \
        float* xb = sm + (BUF) * XK_SZ;                                       \
        float* wb = sm + 2 * XK_SZ + (BUF) * W1_SZ;                           \
        _Pragma("unroll")                                                     \
        for (int it = 0; it < 2; it++) {                                      \
            int m = sa_m + it * 32;                                           \
            float4 v;                                                         \
            v.x = xv[it].x + (pv[it].x - xv[it].x) * tv[it].x;                \
            v.y = xv[it].y + (pv[it].y - xv[it].y) * tv[it].y;                \
            v.z = xv[it].z + (pv[it].z - xv[it].z) * tv[it].z;                \
            v.w = xv[it].w + (pv[it].w - xv[it].w) * tv[it].w;                \
            *(float4*)&xb[m * A1PAD + sa_kq] = v;                             \
        }                                                                     \
        _Pragma("unroll")                                                     \
        for (int it = 0; it < 5; it++)                                        \
            *(float4*)&wb[wk[it] * B1PAD + wn4[it]] = wv[it];                 \
    }

    LDG1(0);

    for (int c = 0; c < nc; c++) {
        STS1(c & 1);
        __syncthreads();
        if (c + 1 < nc) LDG1((c + 1) * KC1);

        const float* xb = sm + (c & 1) * XK_SZ;
        const float* wb = sm + 2 * XK_SZ + (c & 1) * W1_SZ;
        const int r0 = wm * 16 + gq;
#pragma unroll
        for (int ks = 0; ks < 8; ks++) {
            const int k0 = ks * 8;
            float4 af;
            af.x = xb[r0 * A1PAD + k0 + tig];
            af.y = xb[(r0 + 8) * A1PAD + k0 + tig];
            af.z = xb[r0 * A1PAD + k0 + tig + 4];
            af.w = xb[(r0 + 8) * A1PAD + k0 + tig + 4];
#pragma unroll
            for (int j = 0; j < 5; j++) {
                const int n = wn * 40 + j * 8 + gq;
                float2 b;
                b.x = wb[(k0 + tig) * B1PAD + n];
                b.y = wb[(k0 + tig + 4) * B1PAD + n];
                mma_tf32(acc[j], af, b);
            }
        }
    }

    const int r0g = m0g + wm * 16 + gq;
#pragma unroll
    for (int j = 0; j < 5; j++) {
        const int n2 = wn * 20 + j * 4 + tig;
        g_h32[(size_t)r0g * 80 + n2]       = packbf(tanhf(acc[j][0]), tanhf(acc[j][1]));
        g_h32[(size_t)(r0g + 8) * 80 + n2] = packbf(tanhf(acc[j][2]), tanhf(acc[j][3]));
    }
#undef LDG1
#undef STS1
}

// ---------------------------------------------------------------------------
// GEMM2 (bf16): out[m,f,d] = x + sx*(maa_f + h_f @ W2_f)
// 64m x 256d block; bf16 y restage; maa tile in smem; 3 blocks/SM.
// ---------------------------------------------------------------------------
__global__ void __launch_bounds__(T2, 3) k_gemm2(
    const float* __restrict__ x, const float* __restrict__ state,
    const float* __restrict__ W2,
    const float* __restrict__ mk, const float* __restrict__ mw,
    const float* __restrict__ mv, const float* __restrict__ mr,
    const float* __restrict__ mg,
    const int* __restrict__ i_ptr, float* __restrict__ out,
    float* __restrict__ out_state,
    int S, int D, int rows, int has_state, int total4)
{
    extern __shared__ unsigned smu[];
    unsigned* hp32  = smu;                               // [64][HP32]
    unsigned* w2s32 = smu + HP_TOT;                      // [32][WP32]
    unsigned* ys2   = smu + HP_TOT + WP_TOT;             // [5][64][Y2P]
    float*    mas   = (float*)(smu + HP_TOT + WP_TOT + Y2_TOT);  // [5][MAPAD]

    const int m0   = blockIdx.x * BM2;
    const int d0   = blockIdx.y * BN2;
    const int tid  = threadIdx.x;
    const int w    = tid >> 5;
    const int lane = tid & 31;
    const int wm   = w & 3;
    const int wn   = w >> 2;
    const int gq   = lane >> 2;
    const int tig  = lane & 3;
    const int i1   = rows * i_ptr[0] + 1;

    // ---- state copy (distributed over all blocks) ----
    if (has_state) {
        const int nb = gridDim.x * gridDim.y;
        for (int idx = (blockIdx.y * gridDim.x + blockIdx.x) * T2 + tid;
             idx < total4; idx += nb * T2) {
            int e  = idx * 4;
            int dd = e % D;
            int r  = (e / D) % rows;
            int b  = e / (D * rows);
            float4 v;
            if (r == i1)
                v = *(const float4*)&x[((size_t)b * S + (S - 1)) * D + dd];
            else
                v = *(const float4*)&state[e];
            *(float4*)&out_state[e] = v;
        }
    }

    const float* maa[5] = { mk, mw, mv, mr, mg };

    // ---- stage maa tile: 5 x 256 floats ----
#pragma unroll
    for (int it = 0; it < 2; it++) {
        int idx = tid + it * T2;
        if (idx < 320) {
            int f    = idx >> 6;
            int dl4  = (idx & 63) * 4;
            *(float4*)&mas[f * MAPAD + dl4] = *(const float4*)&maa[f][d0 + dl4];
        }
    }

    // ---- stage h once, paired layout ----
#pragma unroll
    for (int it = 0; it < 5; it++) {
        int idx = tid + it * T2;
        int r   = idx / 20;
        int q4  = (idx - r * 20) * 4;
        const uint4 hv = *(const uint4*)&g_h32[(size_t)(m0 + r) * 80 + q4];
        unsigned vals[4] = { hv.x, hv.y, hv.z, hv.w };
#pragma unroll
        for (int e = 0; e < 4; e++) {
            int p   = q4 + e;
            int seg = p >> 3, lp = p & 7;
            hp32[r * HP32 + seg * 8 + (lp & 3) * 2 + (lp >> 2)] = vals[e];
        }
    }

    // epilogue mapping
    const int er  = tid >> 3;
    const int ec4 = (tid & 7) * 4;

    float4 wva[3], wvb[3];

#define LDGW(C)                                                               \
    {                                                                         \
        _Pragma("unroll")                                                     \
        for (int it = 0; it < 3; it++) {                                      \
            int g = tid + it * T2;                                            \
            if (g < 640) {                                                    \
                int kp = g >> 3, n4 = (g & 7) * 4;                            \
                wva[it] = *(const float4*)&W2[(size_t)(2 * kp) * D + d0 + (C) * CW + n4]; \
                wvb[it] = *(const float4*)&W2[(size_t)(2 * kp + 1) * D + d0 + (C) * CW + n4]; \
            }                                                                 \
        }                                                                     \
    }

#define STSW()                                                                \
    {                                                                         \
        _Pragma("unroll")                                                     \
        for (int it = 0; it < 3; it++) {                                      \
            int g = tid + it * T2;                                            \
            if (g < 640) {                                                    \
                int kp = g >> 3, n4 = (g & 7) * 4;                            \
                int seg = kp >> 3, lp = kp & 7;                               \
                int dst = seg * 8 + (lp & 3) * 2 + (lp >> 2);                 \
                w2s32[(n4 + 0) * WP32 + dst] = packbf(wva[it].x, wvb[it].x);  \
                w2s32[(n4 + 1) * WP32 + dst] = packbf(wva[it].y, wvb[it].y);  \
                w2s32[(n4 + 2) * WP32 + dst] = packbf(wva[it].z, wvb[it].z);  \
                w2s32[(n4 + 3) * WP32 + dst] = packbf(wva[it].w, wvb[it].w);  \
            }                                                                 \
        }                                                                     \
    }

    LDGW(0);

    for (int c = 0; c < NCH; c++) {
        STSW();
        __syncthreads();                 // (A) w2s ready; h/maa staging (c==0)
        if (c + 1 < NCH) LDGW(c + 1);

        const int d0c = d0 + c * CW;
        const int r0  = wm * 16 + gq;

        float acc[5][2][4];
#pragma unroll
        for (int f = 0; f < 5; f++)
#pragma unroll
            for (int j = 0; j < 2; j++)
#pragma unroll
                for (int q = 0; q < 4; q++) acc[f][j][q] = 0.f;

#pragma unroll
        for (int f = 0; f < 5; f++) {
#pragma unroll
            for (int ks = 0; ks < 2; ks++) {
                const int seg = f * 2 + ks;
                const uint2 alo = *(const uint2*)&hp32[r0 * HP32 + seg * 8 + tig * 2];
                const uint2 ahi = *(const uint2*)&hp32[(r0 + 8) * HP32 + seg * 8 + tig * 2];
#pragma unroll
                for (int j = 0; j < 2; j++) {
                    const int n = wn * 16 + j * 8 + gq;
                    const uint2 bb = *(const uint2*)&w2s32[n * WP32 + seg * 8 + tig * 2];
                    mma_bf16(acc[f][j], alo.x, ahi.x, alo.y, ahi.y, bb.x, bb.y);
                }
            }
        }

        // ---- restage y fragments to smem (bf16x2) ----
#pragma unroll
        for (int f = 0; f < 5; f++)
#pragma unroll
            for (int j = 0; j < 2; j++) {
                const int cu = wn * 8 + j * 4 + tig;   // u32 col
#pragma unroll
                for (int half = 0; half < 2; half++) {
                    const int row = wm * 16 + gq + half * 8;
                    ys2[(f * BM2 + row) * Y2P + cu] =
                        packbf(acc[f][j][half * 2], acc[f][j][half * 2 + 1]);
                }
            }
        __syncthreads();                 // (B) y ready

        // ---- coalesced epilogue ----
#pragma unroll
        for (int it = 0; it < 2; it++) {
            const int row = er + it * 32;
            const int mr_ = m0 + row;
            const float4 xvv = *(const float4*)&x[(size_t)mr_ * D + d0c + ec4];
            float4 pvv;
            if ((mr_ % S) == 0) {
                int b = mr_ / S;
                pvv = *(const float4*)&state[((size_t)b * rows + i1) * D + d0c + ec4];
            } else {
                pvv = *(const float4*)&x[(size_t)(mr_ - 1) * D + d0c + ec4];
            }
            float4 sxv;
            sxv.x = pvv.x - xvv.x; sxv.y = pvv.y - xvv.y;
            sxv.z = pvv.z - xvv.z; sxv.w = pvv.w - xvv.w;
#pragma unroll
            for (int f = 0; f < 5; f++) {
                const float4 mfv = *(const float4*)&mas[f * MAPAD + c * CW + ec4];
                const uint2 yu = *(const uint2*)&ys2[(f * BM2 + row) * Y2P + (tid & 7) * 2];
                const float2 y0 = unpackbf(yu.x);
                const float2 y1 = unpackbf(yu.y);
                float4 o;
                o.x = xvv.x + sxv.x * (mfv.x + y0.x);
                o.y = xvv.y + sxv.y * (mfv.y + y0.y);
                o.z = xvv.z + sxv.z * (mfv.z + y1.x);
                o.w = xvv.w + sxv.w * (mfv.w + y1.y);
                *(float4*)&out[((size_t)mr_ * 5 + f) * D + d0c + ec4] = o;
            }
        }
    }
#undef LDGW
#undef STSW
}

// ---------------------------------------------------------------------------
extern "C" void kernel_launch(void* const* d_in, const int* in_sizes, int n_in,
                              void* d_out, int out_size)
{
    const float* x     = (const float*)d_in[0];
    const float* state = (const float*)d_in[1];
    const float* tmx   = (const float*)d_in[2];
    const float* W1    = (const float*)d_in[3];
    const float* W2    = (const float*)d_in[4];
    const float* mk    = (const float*)d_in[5];
    const float* mw    = (const float*)d_in[6];
    const float* mv    = (const float*)d_in[7];
    const float* mr    = (const float*)d_in[8];
    const float* mg    = (const float*)d_in[9];
    const int*   ip    = (const int*)d_in[10];

    const int D    = in_sizes[2];          // 2048
    const int M    = in_sizes[0] / D;      // 8192
    const int rows = 2 + D / 32;           // 66
    const int B    = in_sizes[1] / (rows * D);
    const int S    = M / B;

    float* out_x = (float*)d_out;
    const long long xsz = (long long)M * 5 * D;
    const int has_state = ((long long)out_size > xsz) ? 1 : 0;
    float* out_state = out_x + xsz;
    const int total4 = (B * rows * D) / 4;

    const int smem1 = SM1_FLOATS * 4;      // 120832 B
    const int smem2 = SM2_WORDS * 4;       // 70736 B
    static int inited = 0;
    if (!inited) {
        cudaFuncSetAttribute(k_gemm1, cudaFuncAttributeMaxDynamicSharedMemorySize, smem1);
        cudaFuncSetAttribute(k_gemm2, cudaFuncAttributeMaxDynamicSharedMemorySize, smem2);
        inited = 1;
    }

    k_gemm1<<<M / BM1, T1, smem1>>>(x, state, tmx, W1, ip, S, D, rows);

    dim3 g2(M / BM2, D / BN2);
    k_gemm2<<<g2, T2, smem2>>>(x, state, W2, mk, mw, mv, mr, mg, ip,
                               out_x, out_state, S, D, rows,
                               has_state, total4);
}

// round 14
// speedup vs baseline: 1.0828x; 1.0663x over previous
#include <cuda_runtime.h>
#include <cuda_bf16.h>

#define NMIX 160
// gemm1: 64m x 160n, KC=64, 512 threads = 4m x 4n warps, j=5 (tf32)
#define T1    512
#define BM1   64
#define KC1   64
#define A1PAD 68
#define B1PAD 168
#define XK_SZ (BM1 * A1PAD)
#define W1_SZ (KC1 * B1PAD)
#define SM1_FLOATS (2 * XK_SZ + 2 * W1_SZ)       // 120832 B
// gemm2: 64m x 256d blocks; bf16 m16n8k16; W2 in 32-wide chunks
#define T2    256
#define BM2   64
#define BN2   256
#define CW    32
#define NCH   (BN2 / CW)             // 8
#define HP32  104                    // hp row pitch (u32)
#define WP32  104                    // w2s row pitch (u32)
#define Y2P   20                     // ys row pitch (u32, bf16x2)
#define MAPAD 260                    // maa tile row pitch (f32)
#define HP_TOT (BM2 * HP32)                      // 6656 u32
#define WP_TOT (CW * WP32)                       // 3328 u32
#define Y2_TOT (5 * BM2 * Y2P)                   // 6400 u32
#define MA_TOT (5 * MAPAD)                       // 1300 f32
#define SM2_WORDS (HP_TOT + WP_TOT + Y2_TOT + MA_TOT)  // 17684 -> 70736 B

// h = tanh(xk @ W1) packed bf16x2: [M][80] u32, M = 8192
__device__ unsigned g_h32[8192 * 80];

__device__ __forceinline__ void mma_tf32(float* c, const float4& a, const float2& b) {
    const unsigned* A = reinterpret_cast<const unsigned*>(&a);
    const unsigned* B = reinterpret_cast<const unsigned*>(&b);
    asm volatile(
        "mma.sync.aligned.m16n8k8.row.col.f32.tf32.tf32.f32 "
        "{%0,%1,%2,%3},{%4,%5,%6,%7},{%8,%9},{%0,%1,%2,%3};"
        : "+f"(c[0]), "+f"(c[1]), "+f"(c[2]), "+f"(c[3])
        : "r"(A[0]), "r"(A[1]), "r"(A[2]), "r"(A[3]), "r"(B[0]), "r"(B[1]));
}

__device__ __forceinline__ void mma_bf16(float* c, unsigned a0, unsigned a1,
                                         unsigned a2, unsigned a3,
                                         unsigned b0, unsigned b1) {
    asm volatile(
        "mma.sync.aligned.m16n8k16.row.col.f32.bf16.bf16.f32 "
        "{%0,%1,%2,%3},{%4,%5,%6,%7},{%8,%9},{%0,%1,%2,%3};"
        : "+f"(c[0]), "+f"(c[1]), "+f"(c[2]), "+f"(c[3])
        : "r"(a0), "r"(a1), "r"(a2), "r"(a3), "r"(b0), "r"(b1));
}

__device__ __forceinline__ unsigned packbf(float lo, float hi) {
    __nv_bfloat162 v = __float22bfloat162_rn(make_float2(lo, hi));
    return *reinterpret_cast<unsigned*>(&v);
}

__device__ __forceinline__ float2 unpackbf(unsigned u) {
    __nv_bfloat162 v = *reinterpret_cast<__nv_bfloat162*>(&u);
    return __bfloat1622float2(v);
}

// ---------------------------------------------------------------------------
// GEMM1 (tf32): g_h32[m][:] = bf16( tanh( sum_k xk[m,k] * W1[k,n] ) )
// ---------------------------------------------------------------------------
__global__ void __launch_bounds__(T1, 1) k_gemm1(
    const float* __restrict__ x, const float* __restrict__ state,
    const float* __restrict__ tmx, const float* __restrict__ W1,
    const int* __restrict__ i_ptr, int S, int D, int rows)
{
    extern __shared__ float sm[];

    const int m0g  = blockIdx.x * BM1;
    const int tid  = threadIdx.x;
    const int w    = tid >> 5;
    const int lane = tid & 31;
    const int wm   = w & 3;
    const int wn   = w >> 2;
    const int gq   = lane >> 2;
    const int tig  = lane & 3;
    const int i1   = rows * i_ptr[0] + 1;

    const int sa_m  = tid >> 4;
    const int sa_kq = (tid & 15) * 4;

    float acc[5][4];
#pragma unroll
    for (int j = 0; j < 5; j++)
#pragma unroll
        for (int q = 0; q < 4; q++) acc[j][q] = 0.f;

    float4 xv[2], pv[2], tv[2];
    float4 wv[5];
    int    wk[5], wn4[5];

    const int nc = D / KC1;

#define LDG1(KB)                                                              \
    {                                                                         \
        _Pragma("unroll")                                                     \
        for (int it = 0; it < 2; it++) {                                      \
            int m  = sa_m + it * 32;                                          \
            int mg = m0g + m;                                                 \
            int g  = (KB) + sa_kq;                                            \
            xv[it] = *(const float4*)&x[(size_t)mg * D + g];                  \
            if ((mg % S) == 0) {                                              \
                int b = mg / S;                                               \
                pv[it] = *(const float4*)&state[((size_t)b * rows + i1) * D + g]; \
            } else {                                                          \
                pv[it] = *(const float4*)&x[(size_t)(mg - 1) * D + g];        \
            }                                                                 \
            tv[it] = *(const float4*)&tmx[g];                                 \
        }                                                                     \
        _Pragma("unroll")                                                     \
        for (int it = 0; it < 5; it++) {                                      \
            int idx = tid + it * T1;                                          \
            int k   = idx / 40;                                               \
            int n4  = (idx - k * 40) * 4;                                     \
            wk[it] = k; wn4[it] = n4;                                         \
            wv[it] = *(const float4*)&W1[(size_t)((KB) + k) * NMIX + n4];     \
        }                                                                     \
    }

#define STS1(BUF)                                                             \
    {                                                                         \
        float* xb = sm + (BUF) * XK_SZ;                                       \
        float* wb = sm + 2 * XK_SZ + (BUF) * W1_SZ;                           \
        _Pragma("unroll")                                                     \
        for (int it = 0; it < 2; it++) {                                      \
            int m = sa_m + it * 32;                                           \
            float4 v;                                                         \
            v.x = xv[it].x + (pv[it].x - xv[it].x) * tv[it].x;                \
            v.y = xv[it].y + (pv[it].y - xv[it].y) * tv[it].y;                \
            v.z = xv[it].z + (pv[it].z - xv[it].z) * tv[it].z;                \
            v.w = xv[it].w + (pv[it].w - xv[it].w) * tv[it].w;                \
            *(float4*)&xb[m * A1PAD + sa_kq] = v;                             \
        }                                                                     \
        _Pragma("unroll")                                                     \
        for (int it = 0; it < 5; it++)                                        \
            *(float4*)&wb[wk[it] * B1PAD + wn4[it]] = wv[it];                 \
    }

    LDG1(0);

    for (int c = 0; c < nc; c++) {
        STS1(c & 1);
        __syncthreads();
        if (c + 1 < nc) LDG1((c + 1) * KC1);

        const float* xb = sm + (c & 1) * XK_SZ;
        const float* wb = sm + 2 * XK_SZ + (c & 1) * W1_SZ;
        const int r0 = wm * 16 + gq;
#pragma unroll
        for (int ks = 0; ks < 8; ks++) {
            const int k0 = ks * 8;
            float4 af;
            af.x = xb[r0 * A1PAD + k0 + tig];
            af.y = xb[(r0 + 8) * A1PAD + k0 + tig];
            af.z = xb[r0 * A1PAD + k0 + tig + 4];
            af.w = xb[(r0 + 8) * A1PAD + k0 + tig + 4];
#pragma unroll
            for (int j = 0; j < 5; j++) {
                const int n = wn * 40 + j * 8 + gq;
                float2 b;
                b.x = wb[(k0 + tig) * B1PAD + n];
                b.y = wb[(k0 + tig + 4) * B1PAD + n];
                mma_tf32(acc[j], af, b);
            }
        }
    }

    const int r0g = m0g + wm * 16 + gq;
#pragma unroll
    for (int j = 0; j < 5; j++) {
        const int n2 = wn * 20 + j * 4 + tig;
        g_h32[(size_t)r0g * 80 + n2]       = packbf(tanhf(acc[j][0]), tanhf(acc[j][1]));
        g_h32[(size_t)(r0g + 8) * 80 + n2] = packbf(tanhf(acc[j][2]), tanhf(acc[j][3]));
    }
#undef LDG1
#undef STS1
}

// ---------------------------------------------------------------------------
// GEMM2 (bf16): out[m,f,d] = x + sx*(maa_f + h_f @ W2_f)
// 64m x 256d block; x/prev prefetched behind MMA; bf16 y restage.
// ---------------------------------------------------------------------------
__global__ void __launch_bounds__(T2, 2) k_gemm2(
    const float* __restrict__ x, const float* __restrict__ state,
    const float* __restrict__ W2,
    const float* __restrict__ mk, const float* __restrict__ mw,
    const float* __restrict__ mv, const float* __restrict__ mr,
    const float* __restrict__ mg,
    const int* __restrict__ i_ptr, float* __restrict__ out,
    float* __restrict__ out_state,
    int S, int D, int rows, int has_state, int total4)
{
    extern __shared__ unsigned smu[];
    unsigned* hp32  = smu;                               // [64][HP32]
    unsigned* w2s32 = smu + HP_TOT;                      // [32][WP32]
    unsigned* ys2   = smu + HP_TOT + WP_TOT;             // [5][64][Y2P]
    float*    mas   = (float*)(smu + HP_TOT + WP_TOT + Y2_TOT);  // [5][MAPAD]

    const int m0   = blockIdx.x * BM2;
    const int d0   = blockIdx.y * BN2;
    const int tid  = threadIdx.x;
    const int w    = tid >> 5;
    const int lane = tid & 31;
    const int wm   = w & 3;
    const int wn   = w >> 2;
    const int gq   = lane >> 2;
    const int tig  = lane & 3;
    const int i1   = rows * i_ptr[0] + 1;

    // ---- state copy (distributed over all blocks) ----
    if (has_state) {
        const int nb = gridDim.x * gridDim.y;
        for (int idx = (blockIdx.y * gridDim.x + blockIdx.x) * T2 + tid;
             idx < total4; idx += nb * T2) {
            int e  = idx * 4;
            int dd = e % D;
            int r  = (e / D) % rows;
            int b  = e / (D * rows);
            float4 v;
            if (r == i1)
                v = *(const float4*)&x[((size_t)b * S + (S - 1)) * D + dd];
            else
                v = *(const float4*)&state[e];
            *(float4*)&out_state[e] = v;
        }
    }

    const float* maa[5] = { mk, mw, mv, mr, mg };

    // ---- stage maa tile: 5 x 256 floats ----
#pragma unroll
    for (int it = 0; it < 2; it++) {
        int idx = tid + it * T2;
        if (idx < 320) {
            int f    = idx >> 6;
            int dl4  = (idx & 63) * 4;
            *(float4*)&mas[f * MAPAD + dl4] = *(const float4*)&maa[f][d0 + dl4];
        }
    }

    // ---- stage h once, paired layout ----
#pragma unroll
    for (int it = 0; it < 5; it++) {
        int idx = tid + it * T2;
        int r   = idx / 20;
        int q4  = (idx - r * 20) * 4;
        const uint4 hv = *(const uint4*)&g_h32[(size_t)(m0 + r) * 80 + q4];
        unsigned vals[4] = { hv.x, hv.y, hv.z, hv.w };
#pragma unroll
        for (int e = 0; e < 4; e++) {
            int p   = q4 + e;
            int seg = p >> 3, lp = p & 7;
            hp32[r * HP32 + seg * 8 + (lp & 3) * 2 + (lp >> 2)] = vals[e];
        }
    }

    // epilogue mapping
    const int er  = tid >> 3;
    const int ec4 = (tid & 7) * 4;

    float4 wva[3], wvb[3];
    float4 xpr[2], ppr[2];       // prefetched x / prev for current chunk

#define LDGW(C)                                                               \
    {                                                                         \
        _Pragma("unroll")                                                     \
        for (int it = 0; it < 3; it++) {                                      \
            int g = tid + it * T2;                                            \
            if (g < 640) {                                                    \
                int kp = g >> 3, n4 = (g & 7) * 4;                            \
                wva[it] = *(const float4*)&W2[(size_t)(2 * kp) * D + d0 + (C) * CW + n4]; \
                wvb[it] = *(const float4*)&W2[(size_t)(2 * kp + 1) * D + d0 + (C) * CW + n4]; \
            }                                                                 \
        }                                                                     \
    }

#define STSW()                                                                \
    {                                                                         \
        _Pragma("unroll")                                                     \
        for (int it = 0; it < 3; it++) {                                      \
            int g = tid + it * T2;                                            \
            if (g < 640) {                                                    \
                int kp = g >> 3, n4 = (g & 7) * 4;                            \
                int seg = kp >> 3, lp = kp & 7;                               \
                int dst = seg * 8 + (lp & 3) * 2 + (lp >> 2);                 \
                w2s32[(n4 + 0) * WP32 + dst] = packbf(wva[it].x, wvb[it].x);  \
                w2s32[(n4 + 1) * WP32 + dst] = packbf(wva[it].y, wvb[it].y);  \
                w2s32[(n4 + 2) * WP32 + dst] = packbf(wva[it].z, wvb[it].z);  \
                w2s32[(n4 + 3) * WP32 + dst] = packbf(wva[it].w, wvb[it].w);  \
            }                                                                 \
        }                                                                     \
    }

#define LDGX(C)                                                               \
    {                                                                         \
        const int dce = d0 + (C) * CW + ec4;                                  \
        _Pragma("unroll")                                                     \
        for (int it = 0; it < 2; it++) {                                      \
            const int mr_ = m0 + er + it * 32;                                \
            xpr[it] = *(const float4*)&x[(size_t)mr_ * D + dce];              \
            if ((mr_ % S) == 0) {                                             \
                int b = mr_ / S;                                              \
                ppr[it] = *(const float4*)&state[((size_t)b * rows + i1) * D + dce]; \
            } else {                                                          \
                ppr[it] = *(const float4*)&x[(size_t)(mr_ - 1) * D + dce];    \
            }                                                                 \
        }                                                                     \
    }

    LDGW(0);

    for (int c = 0; c < NCH; c++) {
        STSW();
        __syncthreads();                 // (A) w2s ready; h/maa staging (c==0)
        if (c + 1 < NCH) LDGW(c + 1);
        LDGX(c);                         // latency hidden behind MMA + barB

        const int d0c = d0 + c * CW;
        const int r0  = wm * 16 + gq;

        float acc[5][2][4];
#pragma unroll
        for (int f = 0; f < 5; f++)
#pragma unroll
            for (int j = 0; j < 2; j++)
#pragma unroll
                for (int q = 0; q < 4; q++) acc[f][j][q] = 0.f;

#pragma unroll
        for (int f = 0; f < 5; f++) {
#pragma unroll
            for (int ks = 0; ks < 2; ks++) {
                const int seg = f * 2 + ks;
                const uint2 alo = *(const uint2*)&hp32[r0 * HP32 + seg * 8 + tig * 2];
                const uint2 ahi = *(const uint2*)&hp32[(r0 + 8) * HP32 + seg * 8 + tig * 2];
#pragma unroll
                for (int j = 0; j < 2; j++) {
                    const int n = wn * 16 + j * 8 + gq;
                    const uint2 bb = *(const uint2*)&w2s32[n * WP32 + seg * 8 + tig * 2];
                    mma_bf16(acc[f][j], alo.x, ahi.x, alo.y, ahi.y, bb.x, bb.y);
                }
            }
        }

        // ---- restage y fragments to smem (bf16x2) ----
#pragma unroll
        for (int f = 0; f < 5; f++)
#pragma unroll
            for (int j = 0; j < 2; j++) {
                const int cu = wn * 8 + j * 4 + tig;
#pragma unroll
                for (int half = 0; half < 2; half++) {
                    const int row = wm * 16 + gq + half * 8;
                    ys2[(f * BM2 + row) * Y2P + cu] =
                        packbf(acc[f][j][half * 2], acc[f][j][half * 2 + 1]);
                }
            }
        __syncthreads();                 // (B) y ready

        // ---- coalesced epilogue (x/prev already in registers) ----
#pragma unroll
        for (int it = 0; it < 2; it++) {
            const int row = er + it * 32;
            const int mr_ = m0 + row;
            const float4 xvv = xpr[it];
            const float4 pvv = ppr[it];
            float4 sxv;
            sxv.x = pvv.x - xvv.x; sxv.y = pvv.y - xvv.y;
            sxv.z = pvv.z - xvv.z; sxv.w = pvv.w - xvv.w;
#pragma unroll
            for (int f = 0; f < 5; f++) {
                const float4 mfv = *(const float4*)&mas[f * MAPAD + c * CW + ec4];
                const uint2 yu = *(const uint2*)&ys2[(f * BM2 + row) * Y2P + (tid & 7) * 2];
                const float2 y0 = unpackbf(yu.x);
                const float2 y1 = unpackbf(yu.y);
                float4 o;
                o.x = xvv.x + sxv.x * (mfv.x + y0.x);
                o.y = xvv.y + sxv.y * (mfv.y + y0.y);
                o.z = xvv.z + sxv.z * (mfv.z + y1.x);
                o.w = xvv.w + sxv.w * (mfv.w + y1.y);
                *(float4*)&out[((size_t)mr_ * 5 + f) * D + d0c + ec4] = o;
            }
        }
    }
#undef LDGW
#undef STSW
#undef LDGX
}

// ---------------------------------------------------------------------------
extern "C" void kernel_launch(void* const* d_in, const int* in_sizes, int n_in,
                              void* d_out, int out_size)
{
    const float* x     = (const float*)d_in[0];
    const float* state = (const float*)d_in[1];
    const float* tmx   = (const float*)d_in[2];
    const float* W1    = (const float*)d_in[3];
    const float* W2    = (const float*)d_in[4];
    const float* mk    = (const float*)d_in[5];
    const float* mw    = (const float*)d_in[6];
    const float* mv    = (const float*)d_in[7];
    const float* mr    = (const float*)d_in[8];
    const float* mg    = (const float*)d_in[9];
    const int*   ip    = (const int*)d_in[10];

    const int D    = in_sizes[2];          // 2048
    const int M    = in_sizes[0] / D;      // 8192
    const int rows = 2 + D / 32;           // 66
    const int B    = in_sizes[1] / (rows * D);
    const int S    = M / B;

    float* out_x = (float*)d_out;
    const long long xsz = (long long)M * 5 * D;
    const int has_state = ((long long)out_size > xsz) ? 1 : 0;
    float* out_state = out_x + xsz;
    const int total4 = (B * rows * D) / 4;

    const int smem1 = SM1_FLOATS * 4;      // 120832 B
    const int smem2 = SM2_WORDS * 4;       // 70736 B
    static int inited = 0;
    if (!inited) {
        cudaFuncSetAttribute(k_gemm1, cudaFuncAttributeMaxDynamicSharedMemorySize, smem1);
        cudaFuncSetAttribute(k_gemm2, cudaFuncAttributeMaxDynamicSharedMemorySize, smem2);
        inited = 1;
    }

    k_gemm1<<<M / BM1, T1, smem1>>>(x, state, tmx, W1, ip, S, D, rows);

    dim3 g2(M / BM2, D / BN2);
    k_gemm2<<<g2, T2, smem2>>>(x, state, W2, mk, mw, mv, mr, mg, ip,
                               out_x, out_state, S, D, rows,
                               has_state, total4);
}